// round 8
// baseline (speedup 1.0000x reference)
#include <cuda_runtime.h>
#include <cuda_fp16.h>
#include <cstdint>

// Problem constants.
#define NB 8192
#define NH 1024
#define NO 256
#define NE 16

// GEMM tiling: CTA = 64(M) x 128(N), K slabs of 32. ~280 live CTAs -> 2/SM.
#define BM 64
#define BN 128
#define BKS 32
#define NSLAB (NH / BKS)   // 32
#define THREADS 256
#define LDH 40             // halfs per smem row (80 B): conflict-free ldmatrix phases

// --- scratch (no allocs allowed) ---
__device__ int g_bin[NE][NB];
__device__ int g_counts[NE];

// ---------------- fused zero+classify+scatter (single block) ----------------
__global__ __launch_bounds__(1024)
void binzero_kernel(const int* __restrict__ num,
                    const int* __restrict__ c, int cmap_n) {
    __shared__ int cs[1024];
    __shared__ int scnt[NE];
    const int t = threadIdx.x;
    for (int i = t; i < cmap_n && i < 1024; i += 1024) cs[i] = c[i] & (NE - 1);
    if (t < NE) scnt[t] = 0;
    __syncthreads();
    #pragma unroll
    for (int j = 0; j < NB / 1024; j++) {
        int i = t + j * 1024;
        int idx = num[i];
        idx = min(max(idx, 0), cmap_n - 1);
        int e = cs[idx];
        int pos = atomicAdd(&scnt[e], 1);
        g_bin[e][pos] = i;
    }
    __syncthreads();
    if (t < NE) g_counts[t] = scnt[t];
}

// ---------------- helpers ----------------
__device__ __forceinline__ uint32_t smem_u32(const void* p) {
    uint32_t a;
    asm("{ .reg .u64 t; cvta.to.shared.u64 t, %1; cvt.u32.u64 %0, t; }" : "=r"(a) : "l"(p));
    return a;
}

__device__ __forceinline__ void ldsm_x4(uint32_t r[4], uint32_t addr) {
    asm volatile("ldmatrix.sync.aligned.m8n8.x4.shared.b16 {%0,%1,%2,%3}, [%4];"
                 : "=r"(r[0]), "=r"(r[1]), "=r"(r[2]), "=r"(r[3]) : "r"(addr));
}

__device__ __forceinline__ void mma_f16(float c[4], const uint32_t a[4],
                                        uint32_t b0, uint32_t b1) {
    asm volatile(
        "mma.sync.aligned.m16n8k16.row.col.f32.f16.f16.f32 "
        "{%0,%1,%2,%3}, {%4,%5,%6,%7}, {%8,%9}, {%0,%1,%2,%3};"
        : "+f"(c[0]), "+f"(c[1]), "+f"(c[2]), "+f"(c[3])
        : "r"(a[0]), "r"(a[1]), "r"(a[2]), "r"(a[3]), "r"(b0), "r"(b1));
}

__device__ __forceinline__ float sigf(float v) { return 1.f / (1.f + __expf(-v)); }

__device__ __forceinline__ void stage8(__half* dst, float4 v0, float4 v1) {
    __half2 h[4];
    h[0] = __floats2half2_rn(v0.x, v0.y);
    h[1] = __floats2half2_rn(v0.z, v0.w);
    h[2] = __floats2half2_rn(v1.x, v1.y);
    h[3] = __floats2half2_rn(v1.z, v1.w);
    *(uint4*)dst = *(uint4*)&h[0];
}

// ---------------- fp16 tensor-core GEMM + bias + sigmoid ----------------
// grid = (NO/BN=2, NB/BM=128, NE=16); dead tiles exit immediately.
__global__ __launch_bounds__(THREADS, 2)
void gemm_kernel(const float* __restrict__ x,
                 const float* __restrict__ W,
                 const float* __restrict__ bias,
                 float* __restrict__ out) {
    const int e = blockIdx.z;
    const int rows = g_counts[e];
    const int m_start = blockIdx.y * BM;
    if (m_start >= rows) return;
    const int n_start = blockIdx.x * BN;

    __shared__ __half As[2][BM][LDH];   // A[m][k]
    __shared__ __half Bs[2][BN][LDH];   // B[n][k] (k contiguous = col-major for mma)
    __shared__ float  bsm[BN];
    __shared__ int    prm[BM];

    const int t    = threadIdx.x;
    const int lane = t & 31;
    const int wid  = t >> 5;
    const int g    = lane >> 2;
    const int tig  = lane & 3;
    const int g2   = lane >> 3;
    const int lr   = lane & 7;
    const int warp_m = (wid & 1) * 32;    // 2 warps along M (32 rows)
    const int warp_n = (wid >> 1) * 32;   // 4 warps along N (32 cols)

    // staging coords: A: row t>>2 (0..63), quarter t&3 (8 floats); B: row t>>1, half t&1 (16 floats)
    const int arow = t >> 2, aq = t & 3;
    const int brow = t >> 1, bh = t & 1;

    if (t < BN) bsm[t] = bias[e * NO + n_start + t];
    if (t < BM) {
        int m = m_start + t;
        prm[t] = (m < rows) ? g_bin[e][m] : g_bin[e][m_start];
    }
    __syncthreads();

    const float* xs = x + (size_t)prm[arow] * NH + aq * 8;
    const float* ws = W + ((size_t)e * NO + n_start + brow) * NH + bh * 16;

    uint32_t aoff[2], boff[2];
    #pragma unroll
    for (int mf = 0; mf < 2; mf++)
        aoff[mf] = (uint32_t)((warp_m + mf * 16 + (g2 & 1) * 8 + lr) * (LDH * 2) + (g2 >> 1) * 16);
    #pragma unroll
    for (int p = 0; p < 2; p++)
        boff[p] = (uint32_t)((warp_n + p * 16 + (g2 >> 1) * 8 + lr) * (LDH * 2) + (g2 & 1) * 16);

    const uint32_t As_b = smem_u32(As);
    const uint32_t Bs_b = smem_u32(Bs);
    const uint32_t BUFA = BM * LDH * 2;
    const uint32_t BUFB = BN * LDH * 2;

    float acc[2][4][4];
    #pragma unroll
    for (int i = 0; i < 2; i++)
        #pragma unroll
        for (int j = 0; j < 4; j++)
            #pragma unroll
            for (int q = 0; q < 4; q++) acc[i][j][q] = 0.f;

    float4 xa0, xa1, wb[4];
    // prologue: slab 0
    xa0 = ((const float4*)xs)[0];
    xa1 = ((const float4*)xs)[1];
    #pragma unroll
    for (int i = 0; i < 4; i++) wb[i] = ((const float4*)ws)[i];
    stage8(&As[0][arow][aq * 8], xa0, xa1);
    stage8(&Bs[0][brow][bh * 16], wb[0], wb[1]);
    stage8(&Bs[0][brow][bh * 16 + 8], wb[2], wb[3]);
    __syncthreads();

    #pragma unroll 2
    for (int ks = 0; ks < NSLAB; ks++) {
        const int buf = ks & 1;

        if (ks + 1 < NSLAB) {
            const float* xp = xs + (ks + 1) * BKS;
            const float* wp = ws + (ks + 1) * BKS;
            xa0 = ((const float4*)xp)[0];
            xa1 = ((const float4*)xp)[1];
            #pragma unroll
            for (int i = 0; i < 4; i++) wb[i] = ((const float4*)wp)[i];
        }

        const uint32_t ab = As_b + buf * BUFA;
        const uint32_t bb = Bs_b + buf * BUFB;
        #pragma unroll
        for (int kk = 0; kk < 2; kk++) {
            uint32_t a[2][4], b[2][4];
            #pragma unroll
            for (int mf = 0; mf < 2; mf++) ldsm_x4(a[mf], ab + aoff[mf] + kk * 32);
            #pragma unroll
            for (int p = 0; p < 2; p++)   ldsm_x4(b[p], bb + boff[p] + kk * 32);
            #pragma unroll
            for (int mf = 0; mf < 2; mf++)
                #pragma unroll
                for (int nf = 0; nf < 4; nf++)
                    mma_f16(acc[mf][nf], a[mf], b[nf >> 1][(nf & 1) * 2],
                            b[nf >> 1][(nf & 1) * 2 + 1]);
        }

        if (ks + 1 < NSLAB) {
            stage8(&As[buf ^ 1][arow][aq * 8], xa0, xa1);
            stage8(&Bs[buf ^ 1][brow][bh * 16], wb[0], wb[1]);
            stage8(&Bs[buf ^ 1][brow][bh * 16 + 8], wb[2], wb[3]);
        }
        __syncthreads();
    }

    // epilogue: bias + sigmoid, scatter rows through the bin
    #pragma unroll
    for (int mf = 0; mf < 2; mf++) {
        #pragma unroll
        for (int h = 0; h < 2; h++) {
            const int rl = warp_m + mf * 16 + g + h * 8;
            if (m_start + rl < rows) {
                const int orow = prm[rl];
                #pragma unroll
                for (int nf = 0; nf < 4; nf++) {
                    const int col = warp_n + nf * 8 + 2 * tig;
                    float v0 = acc[mf][nf][h * 2 + 0] + bsm[col];
                    float v1 = acc[mf][nf][h * 2 + 1] + bsm[col + 1];
                    float2 o;
                    o.x = sigf(v0);
                    o.y = sigf(v1);
                    *(float2*)&out[(size_t)orow * NO + n_start + col] = o;
                }
            }
        }
    }
}

extern "C" void kernel_launch(void* const* d_in, const int* in_sizes, int n_in,
                              void* d_out, int out_size) {
    const float* x    = (const float*)d_in[0];   // [B, H]
    const float* W    = (const float*)d_in[1];   // [E, O, H]
    const float* bias = (const float*)d_in[2];   // [E, O]
    const int*   num  = (const int*)d_in[3];     // [B]    int32
    const int*   c    = (const int*)d_in[4];     // [CMAP] int32
    float* out = (float*)d_out;                  // [B, O]

    const int cmap_n = in_sizes[4];

    binzero_kernel<<<1, 1024>>>(num, c, cmap_n);

    dim3 grid(NO / BN, NB / BM, NE);   // (2, 128, 16)
    gemm_kernel<<<grid, THREADS>>>(x, W, bias, out);
}

// round 9
// speedup vs baseline: 1.0906x; 1.0906x over previous
#include <cuda_runtime.h>
#include <cuda_fp16.h>
#include <cstdint>

// Problem constants.
#define NB 8192
#define NH 1024
#define NO 256
#define NE 16

// GEMM tiling: CTA = 64(M) x 128(N), K slabs of 32 halfs, 4-stage cp.async pipeline.
#define BM 64
#define BN 128
#define BKS 32
#define NSLAB (NH / BKS)   // 32
#define THREADS 256
#define STAGES 4
#define ROWB 80                         // bytes per smem row (40 halfs): conflict-free ldmatrix
#define A_STAGE_B (BM * ROWB)           // 5120
#define B_STAGE_B (BN * ROWB)           // 10240
#define A_OFF 0
#define B_OFF (STAGES * A_STAGE_B)      // 20480
#define BIAS_OFF (B_OFF + STAGES * B_STAGE_B)   // 61440
#define SMEM_TOTAL (BIAS_OFF + BN * 4)          // 61952

// --- scratch (no allocs allowed) ---
__device__ int    g_perm[NB];           // flat, bin-ordered sample ids
__device__ int    g_off[NE + 1];        // expert offsets into g_perm / xp16
__device__ int    g_counts[NE];
__device__ __half xp16[(NB + BM) * NH]; // x gathered to bin order, fp16 (+pad rows)
__device__ __half W16[NE * NO * NH];    // W in fp16

// ---------------- pass 1: bin + prefix + flat scatter (single block) ----------------
__global__ __launch_bounds__(1024)
void binzero_kernel(const int* __restrict__ num,
                    const int* __restrict__ c, int cmap_n) {
    __shared__ int cs[1024];
    __shared__ int scnt[NE];
    __shared__ int scur[NE];
    const int t = threadIdx.x;
    for (int i = t; i < cmap_n && i < 1024; i += 1024) cs[i] = c[i] & (NE - 1);
    if (t < NE) scnt[t] = 0;
    __syncthreads();
    int le[NB / 1024];
    #pragma unroll
    for (int j = 0; j < NB / 1024; j++) {
        int i = t + j * 1024;
        int idx = num[i];
        idx = min(max(idx, 0), cmap_n - 1);
        le[j] = cs[idx];
        atomicAdd(&scnt[le[j]], 1);
    }
    __syncthreads();
    if (t == 0) {
        int acc = 0;
        g_off[0] = 0;
        #pragma unroll
        for (int e = 0; e < NE; e++) {
            scur[e] = acc;
            acc += scnt[e];
            g_off[e + 1] = acc;
            g_counts[e] = scnt[e];
        }
    }
    __syncthreads();
    #pragma unroll
    for (int j = 0; j < NB / 1024; j++) {
        int pos = atomicAdd(&scur[le[j]], 1);
        g_perm[pos] = t + j * 1024;
    }
}

// ---------------- pass 2: convert W->fp16 and gather x->bin-ordered fp16 ----------------
// grid: blocks [0, NB) = x rows (gathered), [NB, NB+1024) = W chunks of 4096 floats.
__global__ __launch_bounds__(128)
void convert_kernel(const float* __restrict__ x, const float* __restrict__ W) {
    const int b = blockIdx.x;
    const int t = threadIdx.x;
    if (b < NB) {
        const float* src = x + (size_t)g_perm[b] * NH;
        __half* dst = xp16 + (size_t)b * NH;
        const int o = t * 8;
        float4 v0 = *(const float4*)(src + o);
        float4 v1 = *(const float4*)(src + o + 4);
        __half2 h[4];
        h[0] = __floats2half2_rn(v0.x, v0.y);
        h[1] = __floats2half2_rn(v0.z, v0.w);
        h[2] = __floats2half2_rn(v1.x, v1.y);
        h[3] = __floats2half2_rn(v1.z, v1.w);
        *(uint4*)(dst + o) = *(uint4*)h;
    } else {
        const size_t base = (size_t)(b - NB) * 4096;
        #pragma unroll
        for (int i = 0; i < 4; i++) {
            const size_t o = base + (size_t)(i * 128 + t) * 8;
            float4 v0 = *(const float4*)(W + o);
            float4 v1 = *(const float4*)(W + o + 4);
            __half2 h[4];
            h[0] = __floats2half2_rn(v0.x, v0.y);
            h[1] = __floats2half2_rn(v0.z, v0.w);
            h[2] = __floats2half2_rn(v1.x, v1.y);
            h[3] = __floats2half2_rn(v1.z, v1.w);
            *(uint4*)(W16 + o) = *(uint4*)h;
        }
    }
}

// ---------------- helpers ----------------
__device__ __forceinline__ uint32_t smem_u32(const void* p) {
    uint32_t a;
    asm("{ .reg .u64 t; cvta.to.shared.u64 t, %1; cvt.u32.u64 %0, t; }" : "=r"(a) : "l"(p));
    return a;
}

__device__ __forceinline__ void cpasync16(uint32_t dst, const void* src) {
    asm volatile("cp.async.cg.shared.global [%0], [%1], 16;" :: "r"(dst), "l"(src));
}

__device__ __forceinline__ void ldsm_x4(uint32_t r[4], uint32_t addr) {
    asm volatile("ldmatrix.sync.aligned.m8n8.x4.shared.b16 {%0,%1,%2,%3}, [%4];"
                 : "=r"(r[0]), "=r"(r[1]), "=r"(r[2]), "=r"(r[3]) : "r"(addr));
}

__device__ __forceinline__ void mma_f16(float c[4], const uint32_t a[4],
                                        uint32_t b0, uint32_t b1) {
    asm volatile(
        "mma.sync.aligned.m16n8k16.row.col.f32.f16.f16.f32 "
        "{%0,%1,%2,%3}, {%4,%5,%6,%7}, {%8,%9}, {%0,%1,%2,%3};"
        : "+f"(c[0]), "+f"(c[1]), "+f"(c[2]), "+f"(c[3])
        : "r"(a[0]), "r"(a[1]), "r"(a[2]), "r"(a[3]), "r"(b0), "r"(b1));
}

__device__ __forceinline__ float sigf(float v) { return 1.f / (1.f + __expf(-v)); }

// ---------------- pass 3: fp16 tensor-core GEMM + bias + sigmoid ----------------
// grid = (NO/BN=2, NB/BM=128, NE=16); dead tiles exit immediately.
__global__ __launch_bounds__(THREADS, 2)
void gemm_kernel(const float* __restrict__ bias, float* __restrict__ out) {
    const int e = blockIdx.z;
    const int rows = g_counts[e];
    const int m_start = blockIdx.y * BM;
    if (m_start >= rows) return;
    const int n_start = blockIdx.x * BN;
    const int base = g_off[e];

    extern __shared__ char smem[];
    const uint32_t sb = smem_u32(smem);
    float* bsm = (float*)(smem + BIAS_OFF);

    const int t    = threadIdx.x;
    const int lane = t & 31;
    const int wid  = t >> 5;
    const int g    = lane >> 2;
    const int tig  = lane & 3;
    const int g2   = lane >> 3;
    const int lr   = lane & 7;
    const int warp_m = (wid & 1) * 32;
    const int warp_n = (wid >> 1) * 32;

    if (t < BN) bsm[t] = bias[e * NO + n_start + t];

    // cp.async source pointers (contiguous fp16; A row gather already done)
    const __half* agp = xp16 + (size_t)(base + m_start + (t >> 2)) * NH + (t & 3) * 8;
    const __half* bgp0 = W16 + (size_t)(e * NO + n_start + (t >> 1)) * NH + (t & 1) * 16;
    // B jobs: j = t (rows 0..127 halves) and j = t+256
    const uint32_t adst = (uint32_t)((t >> 2) * ROWB + (t & 3) * 16);
    const uint32_t bdst0 = (uint32_t)((t >> 1) * ROWB + (t & 1) * 32);

    // ldmatrix offsets within a stage
    uint32_t aoff[2], boff[2];
    #pragma unroll
    for (int mf = 0; mf < 2; mf++)
        aoff[mf] = (uint32_t)((warp_m + mf * 16 + (g2 & 1) * 8 + lr) * ROWB + (g2 >> 1) * 16);
    #pragma unroll
    for (int p = 0; p < 2; p++)
        boff[p] = (uint32_t)((warp_n + p * 16 + (g2 >> 1) * 8 + lr) * ROWB + (g2 & 1) * 16);

    float acc[2][4][4];
    #pragma unroll
    for (int i = 0; i < 2; i++)
        #pragma unroll
        for (int j = 0; j < 4; j++)
            #pragma unroll
            for (int q = 0; q < 4; q++) acc[i][j][q] = 0.f;

    // issue one slab's cp.asyncs into stage s
    auto issue = [&](int ks, int s) {
        const uint32_t ab = sb + A_OFF + s * A_STAGE_B;
        const uint32_t bb = sb + B_OFF + s * B_STAGE_B;
        cpasync16(ab + adst, agp + ks * BKS);
        cpasync16(bb + bdst0, bgp0 + ks * BKS);
        cpasync16(bb + bdst0 + 16, bgp0 + ks * BKS + 8);
    };

    // prologue: stages 0..2
    #pragma unroll
    for (int s = 0; s < STAGES - 1; s++) {
        issue(s, s);
        asm volatile("cp.async.commit_group;");
    }

    for (int ks = 0; ks < NSLAB; ks++) {
        asm volatile("cp.async.wait_group %0;" :: "n"(STAGES - 2) : "memory");
        __syncthreads();

        const int s = ks & (STAGES - 1);
        const uint32_t ab = sb + A_OFF + s * A_STAGE_B;
        const uint32_t bb = sb + B_OFF + s * B_STAGE_B;
        #pragma unroll
        for (int kk = 0; kk < 2; kk++) {
            uint32_t a[2][4], b[2][4];
            #pragma unroll
            for (int mf = 0; mf < 2; mf++) ldsm_x4(a[mf], ab + aoff[mf] + kk * 32);
            #pragma unroll
            for (int p = 0; p < 2; p++)   ldsm_x4(b[p], bb + boff[p] + kk * 32);
            #pragma unroll
            for (int mf = 0; mf < 2; mf++)
                #pragma unroll
                for (int nf = 0; nf < 4; nf++)
                    mma_f16(acc[mf][nf], a[mf], b[nf >> 1][(nf & 1) * 2],
                            b[nf >> 1][(nf & 1) * 2 + 1]);
        }

        if (ks + STAGES - 1 < NSLAB)
            issue(ks + STAGES - 1, (ks + STAGES - 1) & (STAGES - 1));
        asm volatile("cp.async.commit_group;");   // always commit to keep group count fixed
    }

    // epilogue: bias + sigmoid, scatter rows through g_perm
    #pragma unroll
    for (int mf = 0; mf < 2; mf++) {
        #pragma unroll
        for (int h = 0; h < 2; h++) {
            const int rl = warp_m + mf * 16 + g + h * 8;
            if (m_start + rl < rows) {
                const int orow = g_perm[base + m_start + rl];
                #pragma unroll
                for (int nf = 0; nf < 4; nf++) {
                    const int col = warp_n + nf * 8 + 2 * tig;
                    float v0 = acc[mf][nf][h * 2 + 0] + bsm[col];
                    float v1 = acc[mf][nf][h * 2 + 1] + bsm[col + 1];
                    float2 o;
                    o.x = sigf(v0);
                    o.y = sigf(v1);
                    *(float2*)&out[(size_t)orow * NO + n_start + col] = o;
                }
            }
        }
    }
}

extern "C" void kernel_launch(void* const* d_in, const int* in_sizes, int n_in,
                              void* d_out, int out_size) {
    const float* x    = (const float*)d_in[0];   // [B, H]
    const float* W    = (const float*)d_in[1];   // [E, O, H]
    const float* bias = (const float*)d_in[2];   // [E, O]
    const int*   num  = (const int*)d_in[3];     // [B]    int32
    const int*   c    = (const int*)d_in[4];     // [CMAP] int32
    float* out = (float*)d_out;                  // [B, O]

    const int cmap_n = in_sizes[4];

    cudaFuncSetAttribute(gemm_kernel, cudaFuncAttributeMaxDynamicSharedMemorySize,
                         SMEM_TOTAL);

    binzero_kernel<<<1, 1024>>>(num, c, cmap_n);
    convert_kernel<<<NB + (NE * NO * NH) / 4096, 128>>>(x, W);

    dim3 grid(NO / BN, NB / BM, NE);   // (2, 128, 16)
    gemm_kernel<<<grid, THREADS, SMEM_TOTAL>>>(bias, out);
}